// round 14
// baseline (speedup 1.0000x reference)
#include <cuda_runtime.h>
#include <cstdint>

#define D        512
#define NROWS    65536
#define MCODES   4096
#define BM       128
#define BN       128
#define NKC32    16              // k32 blocks (quant layout)
#define NST      8               // BK=64 stages
#define NT_R     512
#define NT_C     32
#define NGRP     64              // 64-col groups per row
#define THRESH   2.5f

// ---------------- scratch (device globals) -----------------------------------
#define A_BLK 4096               // 128 rows x 32 int8 per (rt,kc32)
#define B_BLK 4096
__device__ __align__(128) unsigned char qA[(size_t)NT_R * NKC32 * A_BLK]; // 32MB
__device__ __align__(128) unsigned char qB[(size_t)NT_C * NKC32 * B_BLK]; // 2MB

__device__ float              g_sA[NROWS];
__device__ float              g_sB[MCODES];
__device__ float              g_halfcsq[MCODES];
__device__ unsigned long long g_cand[(size_t)NROWS * NGRP * 2];  // 67MB
__device__ int                g_idx[NROWS];
__device__ int                g_flag_count;
__device__ int                g_flag_list[NROWS];

// ---------------- helpers ----------------------------------------------------
__device__ __forceinline__ unsigned int f2sortable(float f) {
    unsigned int u = __float_as_uint(f);
    return (u & 0x80000000u) ? ~u : (u | 0x80000000u);
}
__device__ __forceinline__ float sortable2f(unsigned int u) {
    unsigned int b = (u & 0x80000000u) ? (u ^ 0x80000000u) : ~u;
    return __uint_as_float(b);
}
__device__ __forceinline__ unsigned long long packSI(float s, int col) {
    return ((unsigned long long)f2sortable(s) << 32) |
           (unsigned long long)(0xFFFFFFFFu - (unsigned)col);
}
__device__ __forceinline__ void top2merge(unsigned long long& b1, unsigned long long& b2,
                                          unsigned long long o1, unsigned long long o2) {
    if (o1 > b1) { b2 = (b1 > o2) ? b1 : o2; b1 = o1; }
    else if (o1 > b2) { b2 = o1; }
}
__device__ __forceinline__ uint32_t smem_u32(const void* p) {
    uint32_t a;
    asm("{ .reg .u64 t; cvta.to.shared.u64 t, %1; cvt.u32.u64 %0, t; }" : "=r"(a) : "l"(p));
    return a;
}

// float-domain top2 state update (tie handling deferred to rescue via THRESH)
__device__ __forceinline__ void ftop2(float& s1, int& c1, float& s2, int& c2,
                                      float s, int c) {
    if (s > s1) { s2 = s1; c2 = c1; s1 = s; c1 = c; }
    else if (s > s2) { s2 = s; c2 = c; }
}
__device__ __forceinline__ void ftop2m(float& s1, int& c1, float& s2, int& c2,
                                       float t1, int d1, float t2, int d2) {
    if (t1 > s1) {
        if (s1 > t2) { s2 = s1; c2 = c1; } else { s2 = t2; c2 = d2; }
        s1 = t1; c1 = d1;
    } else if (t1 > s2) { s2 = t1; c2 = d1; }
}

// ---------------- cp.async / ldmatrix / mma ----------------------------------
__device__ __forceinline__ void cp16(uint32_t dst, const void* src) {
    asm volatile("cp.async.cg.shared.global [%0], [%1], 16;" :: "r"(dst), "l"(src) : "memory");
}
#define CP_COMMIT() asm volatile("cp.async.commit_group;" ::: "memory")
#define CP_WAIT(N)  asm volatile("cp.async.wait_group %0;" :: "n"(N) : "memory")

#define LDM4(r, addr) \
    asm volatile("ldmatrix.sync.aligned.m8n8.x4.shared.b16 {%0,%1,%2,%3}, [%4];" \
        : "=r"((r)[0]), "=r"((r)[1]), "=r"((r)[2]), "=r"((r)[3]) : "r"(addr))

#define MMAI8(d, a, b0_, b1_) \
    asm volatile("mma.sync.aligned.m16n8k32.row.col.s32.s8.s8.s32 " \
        "{%0,%1,%2,%3},{%4,%5,%6,%7},{%8,%9},{%0,%1,%2,%3};" \
        : "+r"((d)[0]), "+r"((d)[1]), "+r"((d)[2]), "+r"((d)[3]) \
        : "r"((a)[0]), "r"((a)[1]), "r"((a)[2]), "r"((a)[3]), "r"(b0_), "r"(b1_))

// ---------------- stage layout -----------------------------------------------
#define STG    16384
#define NSTAGE 4
#define SMEM_TOTAL (NSTAGE * STG)   // 65536

// ---------------- quantization (single digit) --------------------------------
__device__ __forceinline__ uint32_t pack4(int q0, int q1, int q2, int q3) {
    return (uint32_t)(q0 & 0xFF) | ((uint32_t)(q1 & 0xFF) << 8) |
           ((uint32_t)(q2 & 0xFF) << 16) | ((uint32_t)(q3 & 0xFF) << 24);
}

__device__ __forceinline__ void quant_row(const float* __restrict__ X, int row,
                                          unsigned char* __restrict__ pq,
                                          float* __restrict__ scale_out,
                                          float* __restrict__ halfcsq_out) {
    const int lane = threadIdx.x & 31;
    const float4* xp = (const float4*)(X + (size_t)row * D + lane * 16);
    float4 v[4];
    float amax = 0.f, ssq = 0.f;
    #pragma unroll
    for (int i = 0; i < 4; ++i) {
        v[i] = xp[i];
        amax = fmaxf(amax, fmaxf(fmaxf(fabsf(v[i].x), fabsf(v[i].y)),
                                 fmaxf(fabsf(v[i].z), fabsf(v[i].w))));
        if (halfcsq_out)
            ssq += v[i].x * v[i].x + v[i].y * v[i].y + v[i].z * v[i].z + v[i].w * v[i].w;
    }
    #pragma unroll
    for (int o = 16; o > 0; o >>= 1) {
        amax = fmaxf(amax, __shfl_xor_sync(0xffffffffu, amax, o));
        if (halfcsq_out) ssq += __shfl_xor_sync(0xffffffffu, ssq, o);
    }
    amax = fmaxf(amax, 1e-30f);
    const float inv = 127.f / amax;
    uint32_t H[4];
    #pragma unroll
    for (int i = 0; i < 4; ++i) {
        float f[4] = {v[i].x, v[i].y, v[i].z, v[i].w};
        int qh[4];
        #pragma unroll
        for (int j = 0; j < 4; ++j) {
            qh[j] = __float2int_rn(f[j] * inv);
            qh[j] = max(-127, min(127, qh[j]));
        }
        H[i] = pack4(qh[0], qh[1], qh[2], qh[3]);
    }
    const int rt  = row >> 7;
    const int rIn = row & 127;
    const int kc  = lane >> 1;
    const int c   = lane & 1;
    const size_t off = (size_t)(rt * NKC32 + kc) * 4096 + (size_t)(c * 128 + rIn) * 16;
    *(uint4*)(pq + off) = make_uint4(H[0], H[1], H[2], H[3]);
    if (lane == 0) {
        scale_out[row] = amax / 127.f;
        if (halfcsq_out) halfcsq_out[row] = 0.5f * ssq;
    }
}

__global__ void k_quant_a(const float* __restrict__ A) {
    int row = blockIdx.x * 8 + (threadIdx.x >> 5);
    if (row < NROWS) quant_row(A, row, qA, g_sA, nullptr);
}
__global__ void k_quant_b(const float* __restrict__ B) {
    int row = blockIdx.x * 8 + (threadIdx.x >> 5);
    if (row < MCODES) quant_row(B, row, qB, g_sB, g_halfcsq);
}

__global__ void k_init() { if (threadIdx.x == 0) g_flag_count = 0; }

// ---------------- main GEMM: single-product int8, BK=64 stages ---------------
// 128 thr (4 warps, 2x2), warp tile 64x64, CTA 128x128, 2 CTAs/SM.
__global__ void __launch_bounds__(128, 2)
k_gemm() {
    extern __shared__ char smem[];
    const uint32_t sb = smem_u32(smem);
    const int tid  = threadIdx.x;
    const int wid  = tid >> 5;
    const int lane = tid & 31;
    const int ct = blockIdx.x;           // 0..31 fastest -> B fully L2-resident
    const int rt = blockIdx.y;           // 0..511
    const int wr = wid >> 1;
    const int wc = wid & 1;

    const unsigned char* aP = qA + (size_t)(rt * NKC32) * A_BLK;
    const unsigned char* bP = qB + (size_t)(ct * NKC32) * B_BLK;

    auto load_stage = [&](int s) {
        const uint32_t st = sb + (s & (NSTAGE - 1)) * STG;
        const uint32_t o = tid * 16;
        const unsigned char* pa = aP + (size_t)(2 * s) * A_BLK;
        const unsigned char* pb = bP + (size_t)(2 * s) * B_BLK;
        #pragma unroll
        for (int i = 0; i < 4; ++i)
            cp16(st + o + i * 2048, pa + o + i * 2048);
        #pragma unroll
        for (int i = 0; i < 4; ++i)
            cp16(st + 8192 + o + i * 2048, pb + o + i * 2048);
    };

    const int mtx = lane >> 3;
    const uint32_t aOff = (uint32_t)((mtx >> 1) * 2048 +
                          (wr * 64 + (mtx & 1) * 8 + (lane & 7)) * 16);
    const uint32_t bOff = (uint32_t)(8192 + (mtx & 1) * 2048 +
                          (wc * 64 + (mtx >> 1) * 8 + (lane & 7)) * 16);

    int acc[4][8][4];
    #pragma unroll
    for (int m = 0; m < 4; ++m)
        #pragma unroll
        for (int n = 0; n < 8; ++n)
            #pragma unroll
            for (int q = 0; q < 4; ++q) acc[m][n][q] = 0;

    load_stage(0); CP_COMMIT();
    load_stage(1); CP_COMMIT();
    load_stage(2); CP_COMMIT();

    #pragma unroll 1
    for (int s = 0; s < NST; ++s) {
        if (s < NST - 2)       { CP_WAIT(2); }
        else if (s == NST - 2) { CP_WAIT(1); }
        else                   { CP_WAIT(0); }
        __syncthreads();
        if (s + 3 < NST) { load_stage(s + 3); CP_COMMIT(); }

        const uint32_t st = sb + (s & (NSTAGE - 1)) * STG;
        uint32_t fa0[4][4], fb0[4][4], fa1[4][4], fb1[4][4];
        #pragma unroll
        for (int m = 0; m < 4; ++m) LDM4(fa0[m], st + aOff + (uint32_t)(m * 256));
        #pragma unroll
        for (int j = 0; j < 4; ++j) LDM4(fb0[j], st + bOff + (uint32_t)(j * 256));
        #pragma unroll
        for (int m = 0; m < 4; ++m) LDM4(fa1[m], st + aOff + 4096u + (uint32_t)(m * 256));
        #pragma unroll
        for (int j = 0; j < 4; ++j) LDM4(fb1[j], st + bOff + 4096u + (uint32_t)(j * 256));

        #pragma unroll
        for (int m = 0; m < 4; ++m)
            #pragma unroll
            for (int j = 0; j < 4; ++j) {
                MMAI8(acc[m][2 * j],     fa0[m], fb0[j][0], fb0[j][1]);
                MMAI8(acc[m][2 * j + 1], fa0[m], fb0[j][2], fb0[j][3]);
            }
        #pragma unroll
        for (int m = 0; m < 4; ++m)
            #pragma unroll
            for (int j = 0; j < 4; ++j) {
                MMAI8(acc[m][2 * j],     fa1[m], fb1[j][0], fb1[j][1]);
                MMAI8(acc[m][2 * j + 1], fa1[m], fb1[j][2], fb1[j][3]);
            }
    }

    // ---- epilogue (float domain): per-row top2 over warp's 64 cols ----------
    const int tig = lane & 3;
    const int colBase = ct * BN + wc * 64 + tig * 2;
    float sb2[8][2], hc[8][2];
    #pragma unroll
    for (int nf = 0; nf < 8; ++nf) {
        sb2[nf][0] = __ldg(&g_sB[colBase + nf * 8]);
        sb2[nf][1] = __ldg(&g_sB[colBase + nf * 8 + 1]);
        hc[nf][0]  = __ldg(&g_halfcsq[colBase + nf * 8]);
        hc[nf][1]  = __ldg(&g_halfcsq[colBase + nf * 8 + 1]);
    }
    #pragma unroll
    for (int m = 0; m < 4; ++m) {
        #pragma unroll
        for (int rv = 0; rv < 2; ++rv) {
            const int row = rt * BM + wr * 64 + m * 16 + (lane >> 2) + rv * 8;
            const float sa = __ldg(&g_sA[row]);
            float s1 = -__int_as_float(0x7f800000), s2 = s1;   // -inf
            int c1 = 0, c2 = 0;
            #pragma unroll
            for (int nf = 0; nf < 8; ++nf)
                #pragma unroll
                for (int q = 0; q < 2; ++q) {
                    float t = (float)acc[m][nf][2 * rv + q] * sb2[nf][q];
                    float s = fmaf(t, sa, -hc[nf][q]);
                    ftop2(s1, c1, s2, c2, s, colBase + nf * 8 + q);
                }
            #pragma unroll
            for (int o = 1; o < 4; o <<= 1) {
                float  t1 = __shfl_xor_sync(0xffffffffu, s1, o);
                int    d1 = __shfl_xor_sync(0xffffffffu, c1, o);
                float  t2 = __shfl_xor_sync(0xffffffffu, s2, o);
                int    d2 = __shfl_xor_sync(0xffffffffu, c2, o);
                ftop2m(s1, c1, s2, c2, t1, d1, t2, d2);
            }
            if (tig == 0) {
                const size_t base = ((size_t)row * NGRP + (ct * 2 + wc)) * 2;
                g_cand[base]     = packSI(s1, c1);
                g_cand[base + 1] = packSI(s2, c2);
            }
        }
    }
}

// ---------------- reduce (warp per row) --------------------------------------
__global__ void k_reduce() {
    const int lane = threadIdx.x & 31;
    const int row  = blockIdx.x * 8 + (threadIdx.x >> 5);
    if (row >= NROWS) return;
    const unsigned long long* c = g_cand + (size_t)row * NGRP * 2;
    unsigned long long b1 = 0ull, b2 = 0ull;
    #pragma unroll
    for (int k = 0; k < 4; ++k) {
        unsigned long long v = c[lane + 32 * k];
        top2merge(b1, b2, v, 0ull);
    }
    #pragma unroll
    for (int o = 16; o > 0; o >>= 1) {
        unsigned long long o1 = __shfl_xor_sync(0xffffffffu, b1, o);
        unsigned long long o2 = __shfl_xor_sync(0xffffffffu, b2, o);
        top2merge(b1, b2, o1, o2);
    }
    if (lane == 0) {
        g_idx[row] = (int)(0xFFFFFFFFu - (unsigned)(b1 & 0xFFFFFFFFull));
        float s1 = sortable2f((unsigned)(b1 >> 32));
        float s2 = sortable2f((unsigned)(b2 >> 32));
        if (s1 - s2 < THRESH) {
            int slot = atomicAdd(&g_flag_count, 1);
            if (slot < NROWS) g_flag_list[slot] = row;
        }
    }
}

// ---------------- rescue: exact fp32 re-rank of candidate set ----------------
#define CLIST_MAX 128
__global__ void __launch_bounds__(256)
k_rescue(const float* __restrict__ A, const float* __restrict__ B) {
    __shared__ float xrow[D];
    __shared__ unsigned long long sbest;
    __shared__ int clist[CLIST_MAX];
    __shared__ int ccount;
    const int tid = threadIdx.x, wid = tid >> 5, lid = tid & 31;
    const int count = min(g_flag_count, NROWS);
    for (int i = blockIdx.x; i < count; i += gridDim.x) {
        const int row = g_flag_list[i];
        __syncthreads();
        if (tid == 0) { sbest = 0ull; ccount = 0; }
        for (int j = tid; j < D; j += 256) xrow[j] = A[(size_t)row * D + j];
        __syncthreads();
        const unsigned long long* c = g_cand + (size_t)row * NGRP * 2;
        unsigned long long amax = 0ull;
        for (int e = tid; e < NGRP * 2; e += 256) {
            unsigned long long v = c[e];
            if (v > amax) amax = v;
        }
        atomicMax(&sbest, amax);
        __syncthreads();
        const unsigned thrU = f2sortable(sortable2f((unsigned)(sbest >> 32)) - THRESH);
        for (int e = tid; e < NGRP * 2; e += 256) {
            unsigned long long v = c[e];
            if ((unsigned)(v >> 32) >= thrU) {
                int slot = atomicAdd(&ccount, 1);
                if (slot < CLIST_MAX)
                    clist[slot] = (int)(0xFFFFFFFFu - (unsigned)(v & 0xFFFFFFFFull));
            }
        }
        __syncthreads();
        if (tid == 0) sbest = 0ull;
        __syncthreads();
        const int nc = min(ccount, CLIST_MAX);
        for (int k = wid; k < nc; k += 8) {
            const int m = clist[k];
            const float* cp = B + (size_t)m * D;
            float s = 0.f;
            #pragma unroll
            for (int t = 0; t < 4; ++t) {
                float4 cv = *(const float4*)(cp + t * 128 + lid * 4);
                float4 xv = *(const float4*)(xrow + t * 128 + lid * 4);
                s += cv.x * xv.x + cv.y * xv.y + cv.z * xv.z + cv.w * xv.w;
            }
            #pragma unroll
            for (int o = 16; o > 0; o >>= 1) s += __shfl_xor_sync(0xffffffffu, s, o);
            if (lid == 0) atomicMax(&sbest, packSI(s - __ldg(&g_halfcsq[m]), m));
        }
        __syncthreads();
        if (tid == 0)
            g_idx[row] = (int)(0xFFFFFFFFu - (unsigned)(sbest & 0xFFFFFFFFull));
    }
}

__global__ void k_gather(const float* __restrict__ cb, float* __restrict__ out,
                         float* __restrict__ idx_out) {
    const int n = blockIdx.x * 4 + (threadIdx.x >> 7);
    const int t = threadIdx.x & 127;
    int idx = g_idx[n];
    const float4* src = (const float4*)(cb + (size_t)idx * D);
    float4* dst = (float4*)(out + (size_t)n * D);
    dst[t] = src[t];
    if (t == 0 && idx_out) idx_out[n] = (float)idx;
}

// ---------------- launch ----------------------------------------------------
extern "C" void kernel_launch(void* const* d_in, const int* in_sizes, int n_in,
                              void* d_out, int out_size) {
    const float* emb = (const float*)d_in[0];   // [65536, 512] f32
    const float* cb  = (const float*)d_in[1];   // [4096, 512]  f32
    float* out = (float*)d_out;

    float* idx_out = nullptr;
    long long need = (long long)NROWS * D + NROWS;
    if ((long long)out_size >= need) idx_out = out + (size_t)NROWS * D;

    cudaFuncSetAttribute(k_gemm, cudaFuncAttributeMaxDynamicSharedMemorySize, SMEM_TOTAL);

    k_init<<<1, 32>>>();
    k_quant_a<<<NROWS / 8, 256>>>(emb);
    k_quant_b<<<MCODES / 8, 256>>>(cb);

    dim3 grid(NT_C, NT_R);                      // (32, 512), ct fastest
    k_gemm<<<grid, 128, SMEM_TOTAL>>>();

    k_reduce<<<NROWS / 8, 256>>>();
    k_rescue<<<4096, 256>>>(emb, cb);
    k_gather<<<NROWS / 4, 512>>>(cb, out, idx_out);
}

// round 15
// speedup vs baseline: 1.5540x; 1.5540x over previous
#include <cuda_runtime.h>
#include <cstdint>

#define D        512
#define NROWS    65536
#define MCODES   4096
#define BM       128
#define BN       128
#define NKC32    16              // k32 blocks (quant layout)
#define NST      8               // BK=64 stages
#define NT_R     512
#define NT_C     32
#define NGRP     64              // 64-col groups per row
#define THRESH   2.5f

// ---------------- scratch (device globals) -----------------------------------
#define A_BLK 4096               // 128 rows x 32 int8 per (rt,kc32)
#define B_BLK 4096
__device__ __align__(128) unsigned char qA[(size_t)NT_R * NKC32 * A_BLK]; // 32MB
__device__ __align__(128) unsigned char qB[(size_t)NT_C * NKC32 * B_BLK]; // 2MB

__device__ float        g_sA[NROWS];
__device__ float        g_sB[MCODES];
__device__ float        g_halfcsq[MCODES];
__device__ unsigned int g_cand[(size_t)NROWS * NGRP * 2];  // 33MB, u32 packed
__device__ int          g_idx[NROWS];
__device__ int          g_flag_count;
__device__ int          g_flag_list[NROWS];

// ---------------- helpers ----------------------------------------------------
__device__ __forceinline__ unsigned int f2sortable(float f) {
    unsigned int u = __float_as_uint(f);
    return (u & 0x80000000u) ? ~u : (u | 0x80000000u);
}
__device__ __forceinline__ float sortable2f(unsigned int u) {
    unsigned int b = (u & 0x80000000u) ? (u ^ 0x80000000u) : ~u;
    return __uint_as_float(b);
}
__device__ __forceinline__ unsigned long long packSI(float s, int col) {
    return ((unsigned long long)f2sortable(s) << 32) |
           (unsigned long long)(0xFFFFFFFFu - (unsigned)col);
}
// branchless sortable transform: u ^ (0x80000000 | (u asr 31))
__device__ __forceinline__ unsigned int f2sortable_bl(float f) {
    unsigned int u = __float_as_uint(f);
    return u ^ (0x80000000u | (unsigned int)((int)u >> 31));
}
__device__ __forceinline__ uint32_t smem_u32(const void* p) {
    uint32_t a;
    asm("{ .reg .u64 t; cvta.to.shared.u64 t, %1; cvt.u32.u64 %0, t; }" : "=r"(a) : "l"(p));
    return a;
}

// ---------------- cp.async / ldmatrix / mma ----------------------------------
__device__ __forceinline__ void cp16(uint32_t dst, const void* src) {
    asm volatile("cp.async.cg.shared.global [%0], [%1], 16;" :: "r"(dst), "l"(src) : "memory");
}
#define CP_COMMIT() asm volatile("cp.async.commit_group;" ::: "memory")
#define CP_WAIT(N)  asm volatile("cp.async.wait_group %0;" :: "n"(N) : "memory")

#define LDM4(r, addr) \
    asm volatile("ldmatrix.sync.aligned.m8n8.x4.shared.b16 {%0,%1,%2,%3}, [%4];" \
        : "=r"((r)[0]), "=r"((r)[1]), "=r"((r)[2]), "=r"((r)[3]) : "r"(addr))

#define MMAI8(d, a, b0_, b1_) \
    asm volatile("mma.sync.aligned.m16n8k32.row.col.s32.s8.s8.s32 " \
        "{%0,%1,%2,%3},{%4,%5,%6,%7},{%8,%9},{%0,%1,%2,%3};" \
        : "+r"((d)[0]), "+r"((d)[1]), "+r"((d)[2]), "+r"((d)[3]) \
        : "r"((a)[0]), "r"((a)[1]), "r"((a)[2]), "r"((a)[3]), "r"(b0_), "r"(b1_))

// ---------------- stage layout -----------------------------------------------
#define STG    16384
#define NSTAGE 4
#define SMEM_TOTAL (NSTAGE * STG)   // 65536

// ---------------- quantization (single digit) --------------------------------
__device__ __forceinline__ uint32_t pack4(int q0, int q1, int q2, int q3) {
    return (uint32_t)(q0 & 0xFF) | ((uint32_t)(q1 & 0xFF) << 8) |
           ((uint32_t)(q2 & 0xFF) << 16) | ((uint32_t)(q3 & 0xFF) << 24);
}

__device__ __forceinline__ void quant_row(const float* __restrict__ X, int row,
                                          unsigned char* __restrict__ pq,
                                          float* __restrict__ scale_out,
                                          float* __restrict__ halfcsq_out) {
    const int lane = threadIdx.x & 31;
    const float4* xp = (const float4*)(X + (size_t)row * D + lane * 16);
    float4 v[4];
    float amax = 0.f, ssq = 0.f;
    #pragma unroll
    for (int i = 0; i < 4; ++i) {
        v[i] = xp[i];
        amax = fmaxf(amax, fmaxf(fmaxf(fabsf(v[i].x), fabsf(v[i].y)),
                                 fmaxf(fabsf(v[i].z), fabsf(v[i].w))));
        if (halfcsq_out)
            ssq += v[i].x * v[i].x + v[i].y * v[i].y + v[i].z * v[i].z + v[i].w * v[i].w;
    }
    #pragma unroll
    for (int o = 16; o > 0; o >>= 1) {
        amax = fmaxf(amax, __shfl_xor_sync(0xffffffffu, amax, o));
        if (halfcsq_out) ssq += __shfl_xor_sync(0xffffffffu, ssq, o);
    }
    amax = fmaxf(amax, 1e-30f);
    const float inv = 127.f / amax;
    uint32_t H[4];
    #pragma unroll
    for (int i = 0; i < 4; ++i) {
        float f[4] = {v[i].x, v[i].y, v[i].z, v[i].w};
        int qh[4];
        #pragma unroll
        for (int j = 0; j < 4; ++j) {
            qh[j] = __float2int_rn(f[j] * inv);
            qh[j] = max(-127, min(127, qh[j]));
        }
        H[i] = pack4(qh[0], qh[1], qh[2], qh[3]);
    }
    const int rt  = row >> 7;
    const int rIn = row & 127;
    const int kc  = lane >> 1;
    const int c   = lane & 1;
    const size_t off = (size_t)(rt * NKC32 + kc) * 4096 + (size_t)(c * 128 + rIn) * 16;
    *(uint4*)(pq + off) = make_uint4(H[0], H[1], H[2], H[3]);
    if (lane == 0) {
        scale_out[row] = amax / 127.f;
        if (halfcsq_out) halfcsq_out[row] = 0.5f * ssq;
    }
}

__global__ void k_quant_a(const float* __restrict__ A) {
    int row = blockIdx.x * 8 + (threadIdx.x >> 5);
    if (row < NROWS) quant_row(A, row, qA, g_sA, nullptr);
}
__global__ void k_quant_b(const float* __restrict__ B) {
    int row = blockIdx.x * 8 + (threadIdx.x >> 5);
    if (row < MCODES) quant_row(B, row, qB, g_sB, g_halfcsq);
}

__global__ void k_init() { if (threadIdx.x == 0) g_flag_count = 0; }

// ---------------- main GEMM: single-product int8, BK=64 stages ---------------
// 128 thr (4 warps, 2x2), warp tile 64x64, CTA 128x128, 2 CTAs/SM.
__global__ void __launch_bounds__(128, 2)
k_gemm() {
    extern __shared__ char smem[];
    const uint32_t sb = smem_u32(smem);
    const int tid  = threadIdx.x;
    const int wid  = tid >> 5;
    const int lane = tid & 31;
    const int ct = blockIdx.x;           // 0..31 fastest -> B fully L2-resident
    const int rt = blockIdx.y;           // 0..511
    const int wr = wid >> 1;
    const int wc = wid & 1;

    const unsigned char* aP = qA + (size_t)(rt * NKC32) * A_BLK;
    const unsigned char* bP = qB + (size_t)(ct * NKC32) * B_BLK;

    auto load_stage = [&](int s) {
        const uint32_t st = sb + (s & (NSTAGE - 1)) * STG;
        const uint32_t o = tid * 16;
        const unsigned char* pa = aP + (size_t)(2 * s) * A_BLK;
        const unsigned char* pb = bP + (size_t)(2 * s) * B_BLK;
        #pragma unroll
        for (int i = 0; i < 4; ++i)
            cp16(st + o + i * 2048, pa + o + i * 2048);
        #pragma unroll
        for (int i = 0; i < 4; ++i)
            cp16(st + 8192 + o + i * 2048, pb + o + i * 2048);
    };

    const int mtx = lane >> 3;
    const uint32_t aOff = (uint32_t)((mtx >> 1) * 2048 +
                          (wr * 64 + (mtx & 1) * 8 + (lane & 7)) * 16);
    const uint32_t bOff = (uint32_t)(8192 + (mtx & 1) * 2048 +
                          (wc * 64 + (mtx >> 1) * 8 + (lane & 7)) * 16);

    int acc[4][8][4];
    #pragma unroll
    for (int m = 0; m < 4; ++m)
        #pragma unroll
        for (int n = 0; n < 8; ++n)
            #pragma unroll
            for (int q = 0; q < 4; ++q) acc[m][n][q] = 0;

    load_stage(0); CP_COMMIT();
    load_stage(1); CP_COMMIT();
    load_stage(2); CP_COMMIT();

    #pragma unroll 1
    for (int s = 0; s < NST; ++s) {
        if (s < NST - 2)       { CP_WAIT(2); }
        else if (s == NST - 2) { CP_WAIT(1); }
        else                   { CP_WAIT(0); }
        __syncthreads();
        if (s + 3 < NST) { load_stage(s + 3); CP_COMMIT(); }

        const uint32_t st = sb + (s & (NSTAGE - 1)) * STG;
        uint32_t fa0[4][4], fb0[4][4], fa1[4][4], fb1[4][4];
        #pragma unroll
        for (int m = 0; m < 4; ++m) LDM4(fa0[m], st + aOff + (uint32_t)(m * 256));
        #pragma unroll
        for (int j = 0; j < 4; ++j) LDM4(fb0[j], st + bOff + (uint32_t)(j * 256));
        #pragma unroll
        for (int m = 0; m < 4; ++m) LDM4(fa1[m], st + aOff + 4096u + (uint32_t)(m * 256));
        #pragma unroll
        for (int j = 0; j < 4; ++j) LDM4(fb1[j], st + bOff + 4096u + (uint32_t)(j * 256));

        #pragma unroll
        for (int m = 0; m < 4; ++m)
            #pragma unroll
            for (int j = 0; j < 4; ++j) {
                MMAI8(acc[m][2 * j],     fa0[m], fb0[j][0], fb0[j][1]);
                MMAI8(acc[m][2 * j + 1], fa0[m], fb0[j][2], fb0[j][3]);
            }
        #pragma unroll
        for (int m = 0; m < 4; ++m)
            #pragma unroll
            for (int j = 0; j < 4; ++j) {
                MMAI8(acc[m][2 * j],     fa1[m], fb1[j][0], fb1[j][1]);
                MMAI8(acc[m][2 * j + 1], fa1[m], fb1[j][2], fb1[j][3]);
            }
    }

    // ---- epilogue: branchless u32-packed top2 over warp's 64 cols -----------
    // pack = (sortable_score & 0xFFFFF000) | (4095 - col). Truncation <= ~0.12
    // absolute, far under THRESH; within-THRESH cases rescued exactly.
    const int tig = lane & 3;
    const int colBase = ct * BN + wc * 64 + tig * 2;
    const unsigned invBase = 4095u - (unsigned)colBase;
    float sb2[8][2], hc[8][2];
    #pragma unroll
    for (int nf = 0; nf < 8; ++nf) {
        sb2[nf][0] = __ldg(&g_sB[colBase + nf * 8]);
        sb2[nf][1] = __ldg(&g_sB[colBase + nf * 8 + 1]);
        hc[nf][0]  = __ldg(&g_halfcsq[colBase + nf * 8]);
        hc[nf][1]  = __ldg(&g_halfcsq[colBase + nf * 8 + 1]);
    }
    #pragma unroll
    for (int m = 0; m < 4; ++m) {
        #pragma unroll
        for (int rv = 0; rv < 2; ++rv) {
            const int row = rt * BM + wr * 64 + m * 16 + (lane >> 2) + rv * 8;
            const float sa = __ldg(&g_sA[row]);
            unsigned b1 = 0u, b2 = 0u;
            #pragma unroll
            for (int nf = 0; nf < 8; ++nf)
                #pragma unroll
                for (int q = 0; q < 2; ++q) {
                    float t = (float)acc[m][nf][2 * rv + q] * sb2[nf][q];
                    float s = fmaf(t, sa, -hc[nf][q]);
                    unsigned p = (f2sortable_bl(s) & 0xFFFFF000u) |
                                 (invBase - (unsigned)(nf * 8 + q));
                    b2 = max(b2, min(b1, p));
                    b1 = max(b1, p);
                }
            #pragma unroll
            for (int o = 1; o < 4; o <<= 1) {
                unsigned o1 = __shfl_xor_sync(0xffffffffu, b1, o);
                unsigned o2 = __shfl_xor_sync(0xffffffffu, b2, o);
                b2 = max(max(b2, o2), min(b1, o1));
                b1 = max(b1, o1);
            }
            if (tig == 0) {
                const size_t base = ((size_t)row * NGRP + (ct * 2 + wc)) * 2;
                g_cand[base]     = b1;
                g_cand[base + 1] = b2;
            }
        }
    }
}

// ---------------- reduce (warp per row, u32 branchless) ----------------------
__global__ void k_reduce() {
    const int lane = threadIdx.x & 31;
    const int row  = blockIdx.x * 8 + (threadIdx.x >> 5);
    if (row >= NROWS) return;
    const unsigned* c = g_cand + (size_t)row * NGRP * 2;
    unsigned b1 = 0u, b2 = 0u;
    #pragma unroll
    for (int k = 0; k < 4; ++k) {
        unsigned v = c[lane + 32 * k];
        b2 = max(b2, min(b1, v));
        b1 = max(b1, v);
    }
    #pragma unroll
    for (int o = 16; o > 0; o >>= 1) {
        unsigned o1 = __shfl_xor_sync(0xffffffffu, b1, o);
        unsigned o2 = __shfl_xor_sync(0xffffffffu, b2, o);
        b2 = max(max(b2, o2), min(b1, o1));
        b1 = max(b1, o1);
    }
    if (lane == 0) {
        g_idx[row] = 4095 - (int)(b1 & 0xFFFu);
        float s1 = sortable2f(b1 & 0xFFFFF000u);
        float s2 = sortable2f(b2 & 0xFFFFF000u);
        if (s1 - s2 < THRESH) {
            int slot = atomicAdd(&g_flag_count, 1);
            if (slot < NROWS) g_flag_list[slot] = row;
        }
    }
}

// ---------------- rescue: exact fp32 re-rank of candidate set ----------------
#define CLIST_MAX 128
__global__ void __launch_bounds__(256)
k_rescue(const float* __restrict__ A, const float* __restrict__ B) {
    __shared__ float xrow[D];
    __shared__ unsigned samax;
    __shared__ unsigned long long sbest;
    __shared__ int clist[CLIST_MAX];
    __shared__ int ccount;
    const int tid = threadIdx.x, wid = tid >> 5, lid = tid & 31;
    const int count = min(g_flag_count, NROWS);
    for (int i = blockIdx.x; i < count; i += gridDim.x) {
        const int row = g_flag_list[i];
        __syncthreads();
        if (tid == 0) { samax = 0u; sbest = 0ull; ccount = 0; }
        for (int j = tid; j < D; j += 256) xrow[j] = A[(size_t)row * D + j];
        __syncthreads();
        const unsigned* c = g_cand + (size_t)row * NGRP * 2;
        unsigned amax = 0u;
        for (int e = tid; e < NGRP * 2; e += 256) {
            unsigned v = c[e];
            if (v > amax) amax = v;
        }
        atomicMax(&samax, amax);
        __syncthreads();
        const unsigned thrU =
            f2sortable(sortable2f(samax & 0xFFFFF000u) - THRESH) & 0xFFFFF000u;
        for (int e = tid; e < NGRP * 2; e += 256) {
            unsigned v = c[e];
            if ((v & 0xFFFFF000u) >= thrU) {
                int slot = atomicAdd(&ccount, 1);
                if (slot < CLIST_MAX)
                    clist[slot] = 4095 - (int)(v & 0xFFFu);
            }
        }
        __syncthreads();
        const int nc = min(ccount, CLIST_MAX);
        for (int k = wid; k < nc; k += 8) {
            const int m = clist[k];
            const float* cp = B + (size_t)m * D;
            float s = 0.f;
            #pragma unroll
            for (int t = 0; t < 4; ++t) {
                float4 cv = *(const float4*)(cp + t * 128 + lid * 4);
                float4 xv = *(const float4*)(xrow + t * 128 + lid * 4);
                s += cv.x * xv.x + cv.y * xv.y + cv.z * xv.z + cv.w * xv.w;
            }
            #pragma unroll
            for (int o = 16; o > 0; o >>= 1) s += __shfl_xor_sync(0xffffffffu, s, o);
            if (lid == 0) atomicMax(&sbest, packSI(s - __ldg(&g_halfcsq[m]), m));
        }
        __syncthreads();
        if (tid == 0)
            g_idx[row] = (int)(0xFFFFFFFFu - (unsigned)(sbest & 0xFFFFFFFFull));
    }
}

__global__ void k_gather(const float* __restrict__ cb, float* __restrict__ out,
                         float* __restrict__ idx_out) {
    int n = blockIdx.x;
    int idx = g_idx[n];
    const float4* src = (const float4*)(cb + (size_t)idx * D);
    float4* dst = (float4*)(out + (size_t)n * D);
    dst[threadIdx.x] = src[threadIdx.x];
    if (threadIdx.x == 0 && idx_out) idx_out[n] = (float)idx;
}

// ---------------- launch ----------------------------------------------------
extern "C" void kernel_launch(void* const* d_in, const int* in_sizes, int n_in,
                              void* d_out, int out_size) {
    const float* emb = (const float*)d_in[0];   // [65536, 512] f32
    const float* cb  = (const float*)d_in[1];   // [4096, 512]  f32
    float* out = (float*)d_out;

    float* idx_out = nullptr;
    long long need = (long long)NROWS * D + NROWS;
    if ((long long)out_size >= need) idx_out = out + (size_t)NROWS * D;

    cudaFuncSetAttribute(k_gemm, cudaFuncAttributeMaxDynamicSharedMemorySize, SMEM_TOTAL);

    k_init<<<1, 32>>>();
    k_quant_a<<<NROWS / 8, 256>>>(emb);
    k_quant_b<<<MCODES / 8, 256>>>(cb);

    dim3 grid(NT_C, NT_R);                      // (32, 512), ct fastest
    k_gemm<<<grid, 128, SMEM_TOTAL>>>();

    k_reduce<<<NROWS / 8, 256>>>();
    k_rescue<<<4096, 256>>>(emb, cb);
    k_gather<<<NROWS, 128>>>(cb, out, idx_out);
}

// round 16
// speedup vs baseline: 1.6101x; 1.0361x over previous
#include <cuda_runtime.h>
#include <cstdint>

#define D        512
#define NROWS    65536
#define MCODES   4096
#define BM       128
#define BN       128
#define NKC32    16              // k32 blocks (quant layout)
#define NST      8               // BK=64 stages
#define NT_R     512
#define NT_C     32
#define NGRP     64              // 64-col groups per row
#define THRESH   2.5f

// ---------------- scratch (device globals) -----------------------------------
#define A_BLK 4096               // 128 rows x 32 int8 per (rt,kc32)
#define B_BLK 4096
__device__ __align__(128) unsigned char qA[(size_t)NT_R * NKC32 * A_BLK]; // 32MB
__device__ __align__(128) unsigned char qB[(size_t)NT_C * NKC32 * B_BLK]; // 2MB

__device__ float        g_sA[NROWS];
__device__ float        g_sB[MCODES];
__device__ float        g_halfcsq[MCODES];
__device__ unsigned int g_cand[(size_t)NROWS * NGRP * 2];  // 33MB, u32 packed
__device__ int          g_idx[NROWS];
__device__ int          g_flag_count;
__device__ int          g_flag_list[NROWS];

// ---------------- helpers ----------------------------------------------------
__device__ __forceinline__ unsigned int f2sortable(float f) {
    unsigned int u = __float_as_uint(f);
    return (u & 0x80000000u) ? ~u : (u | 0x80000000u);
}
__device__ __forceinline__ float sortable2f(unsigned int u) {
    unsigned int b = (u & 0x80000000u) ? (u ^ 0x80000000u) : ~u;
    return __uint_as_float(b);
}
__device__ __forceinline__ unsigned long long packSI(float s, int col) {
    return ((unsigned long long)f2sortable(s) << 32) |
           (unsigned long long)(0xFFFFFFFFu - (unsigned)col);
}
__device__ __forceinline__ unsigned int f2sortable_bl(float f) {
    unsigned int u = __float_as_uint(f);
    return u ^ (0x80000000u | (unsigned int)((int)u >> 31));
}
__device__ __forceinline__ uint32_t smem_u32(const void* p) {
    uint32_t a;
    asm("{ .reg .u64 t; cvta.to.shared.u64 t, %1; cvt.u32.u64 %0, t; }" : "=r"(a) : "l"(p));
    return a;
}

// ---------------- cp.async / ldmatrix / mma ----------------------------------
__device__ __forceinline__ void cp16(uint32_t dst, const void* src) {
    asm volatile("cp.async.cg.shared.global [%0], [%1], 16;" :: "r"(dst), "l"(src) : "memory");
}
#define CP_COMMIT() asm volatile("cp.async.commit_group;" ::: "memory")
#define CP_WAIT(N)  asm volatile("cp.async.wait_group %0;" :: "n"(N) : "memory")

#define LDM4(r, addr) \
    asm volatile("ldmatrix.sync.aligned.m8n8.x4.shared.b16 {%0,%1,%2,%3}, [%4];" \
        : "=r"((r)[0]), "=r"((r)[1]), "=r"((r)[2]), "=r"((r)[3]) : "r"(addr))

#define MMAI8(d, a, b0_, b1_) \
    asm volatile("mma.sync.aligned.m16n8k32.row.col.s32.s8.s8.s32 " \
        "{%0,%1,%2,%3},{%4,%5,%6,%7},{%8,%9},{%0,%1,%2,%3};" \
        : "+r"((d)[0]), "+r"((d)[1]), "+r"((d)[2]), "+r"((d)[3]) \
        : "r"((a)[0]), "r"((a)[1]), "r"((a)[2]), "r"((a)[3]), "r"(b0_), "r"(b1_))

// ---------------- stage layout -----------------------------------------------
#define STG    16384
#define NSTAGE 4
#define SMEM_TOTAL (NSTAGE * STG)   // 65536

// ---------------- quantization (single digit) --------------------------------
__device__ __forceinline__ uint32_t pack4(int q0, int q1, int q2, int q3) {
    return (uint32_t)(q0 & 0xFF) | ((uint32_t)(q1 & 0xFF) << 8) |
           ((uint32_t)(q2 & 0xFF) << 16) | ((uint32_t)(q3 & 0xFF) << 24);
}

__device__ __forceinline__ void quant_row(const float* __restrict__ X, int row,
                                          unsigned char* __restrict__ pq,
                                          float* __restrict__ scale_out,
                                          float* __restrict__ halfcsq_out) {
    const int lane = threadIdx.x & 31;
    const float4* xp = (const float4*)(X + (size_t)row * D + lane * 16);
    float4 v[4];
    float amax = 0.f, ssq = 0.f;
    #pragma unroll
    for (int i = 0; i < 4; ++i) {
        v[i] = xp[i];
        amax = fmaxf(amax, fmaxf(fmaxf(fabsf(v[i].x), fabsf(v[i].y)),
                                 fmaxf(fabsf(v[i].z), fabsf(v[i].w))));
        if (halfcsq_out)
            ssq += v[i].x * v[i].x + v[i].y * v[i].y + v[i].z * v[i].z + v[i].w * v[i].w;
    }
    #pragma unroll
    for (int o = 16; o > 0; o >>= 1) {
        amax = fmaxf(amax, __shfl_xor_sync(0xffffffffu, amax, o));
        if (halfcsq_out) ssq += __shfl_xor_sync(0xffffffffu, ssq, o);
    }
    amax = fmaxf(amax, 1e-30f);
    const float inv = 127.f / amax;
    uint32_t H[4];
    #pragma unroll
    for (int i = 0; i < 4; ++i) {
        float f[4] = {v[i].x, v[i].y, v[i].z, v[i].w};
        int qh[4];
        #pragma unroll
        for (int j = 0; j < 4; ++j) {
            qh[j] = __float2int_rn(f[j] * inv);
            qh[j] = max(-127, min(127, qh[j]));
        }
        H[i] = pack4(qh[0], qh[1], qh[2], qh[3]);
    }
    const int rt  = row >> 7;
    const int rIn = row & 127;
    const int kc  = lane >> 1;
    const int c   = lane & 1;
    const size_t off = (size_t)(rt * NKC32 + kc) * 4096 + (size_t)(c * 128 + rIn) * 16;
    *(uint4*)(pq + off) = make_uint4(H[0], H[1], H[2], H[3]);
    if (lane == 0) {
        scale_out[row] = amax / 127.f;
        if (halfcsq_out) halfcsq_out[row] = 0.5f * ssq;
    }
}

__global__ void k_quant_a(const float* __restrict__ A) {
    int row = blockIdx.x * 8 + (threadIdx.x >> 5);
    if (row < NROWS) quant_row(A, row, qA, g_sA, nullptr);
}
__global__ void k_quant_b(const float* __restrict__ B) {
    int row = blockIdx.x * 8 + (threadIdx.x >> 5);
    if (row < MCODES) quant_row(B, row, qB, g_sB, g_halfcsq);
}

__global__ void k_init() { if (threadIdx.x == 0) g_flag_count = 0; }

// ---------------- main GEMM: slice-level software pipeline -------------------
// 128 thr (4 warps, 2x2), warp tile 64x64, CTA 128x128, 2 CTAs/SM.
// Two fragment buffers (A/B); each LDSM burst overlaps the previous 32 mmas.
__global__ void __launch_bounds__(128, 2)
k_gemm() {
    extern __shared__ char smem[];
    const uint32_t sb = smem_u32(smem);
    const int tid  = threadIdx.x;
    const int wid  = tid >> 5;
    const int lane = tid & 31;
    const int ct = blockIdx.x;           // 0..31 fastest -> B fully L2-resident
    const int rt = blockIdx.y;           // 0..511
    const int wr = wid >> 1;
    const int wc = wid & 1;

    const unsigned char* aP = qA + (size_t)(rt * NKC32) * A_BLK;
    const unsigned char* bP = qB + (size_t)(ct * NKC32) * B_BLK;

    auto load_stage = [&](int s) {
        const uint32_t st = sb + (s & (NSTAGE - 1)) * STG;
        const uint32_t o = tid * 16;
        const unsigned char* pa = aP + (size_t)(2 * s) * A_BLK;
        const unsigned char* pb = bP + (size_t)(2 * s) * B_BLK;
        #pragma unroll
        for (int i = 0; i < 4; ++i)
            cp16(st + o + i * 2048, pa + o + i * 2048);
        #pragma unroll
        for (int i = 0; i < 4; ++i)
            cp16(st + 8192 + o + i * 2048, pb + o + i * 2048);
    };

    const int mtx = lane >> 3;
    const uint32_t aOff = (uint32_t)((mtx >> 1) * 2048 +
                          (wr * 64 + (mtx & 1) * 8 + (lane & 7)) * 16);
    const uint32_t bOff = (uint32_t)(8192 + (mtx & 1) * 2048 +
                          (wc * 64 + (mtx >> 1) * 8 + (lane & 7)) * 16);

    int acc[4][8][4];
    #pragma unroll
    for (int m = 0; m < 4; ++m)
        #pragma unroll
        for (int n = 0; n < 8; ++n)
            #pragma unroll
            for (int q = 0; q < 4; ++q) acc[m][n][q] = 0;

    load_stage(0); CP_COMMIT();
    load_stage(1); CP_COMMIT();
    load_stage(2); CP_COMMIT();

    uint32_t fam[2][4][4], fbm[2][4][4];     // two fragment buffers

    // prologue: stage 0 slice 0 -> buffer 0
    CP_WAIT(2);
    __syncthreads();
    #pragma unroll
    for (int m = 0; m < 4; ++m) LDM4(fam[0][m], sb + aOff + (uint32_t)(m * 256));
    #pragma unroll
    for (int j = 0; j < 4; ++j) LDM4(fbm[0][j], sb + bOff + (uint32_t)(j * 256));

    #pragma unroll 1
    for (int s = 0; s < NST; ++s) {
        const uint32_t st = sb + (s & (NSTAGE - 1)) * STG;
        // LDSM buffer1 <- stage s slice1 (overlaps MMA on buffer0)
        #pragma unroll
        for (int m = 0; m < 4; ++m) LDM4(fam[1][m], st + aOff + 4096u + (uint32_t)(m * 256));
        #pragma unroll
        for (int j = 0; j < 4; ++j) LDM4(fbm[1][j], st + bOff + 4096u + (uint32_t)(j * 256));
        // MMA slice0 (buffer0)
        #pragma unroll
        for (int m = 0; m < 4; ++m)
            #pragma unroll
            for (int j = 0; j < 4; ++j) {
                MMAI8(acc[m][2 * j],     fam[0][m], fbm[0][j][0], fbm[0][j][1]);
                MMAI8(acc[m][2 * j + 1], fam[0][m], fbm[0][j][2], fbm[0][j][3]);
            }
        if (s + 1 < NST) {
            // safe before barrier: stage (s-1)&3's reads all completed before
            // the barrier of iter s-1, which precedes this store.
            if (s + 3 < NST) { load_stage(s + 3); CP_COMMIT(); }
            if (s < NST - 3)       { CP_WAIT(2); }
            else if (s == NST - 3) { CP_WAIT(1); }
            else                   { CP_WAIT(0); }
            __syncthreads();
            const uint32_t stn = sb + ((s + 1) & (NSTAGE - 1)) * STG;
            // LDSM buffer0 <- stage s+1 slice0 (overlaps MMA on buffer1)
            #pragma unroll
            for (int m = 0; m < 4; ++m) LDM4(fam[0][m], stn + aOff + (uint32_t)(m * 256));
            #pragma unroll
            for (int j = 0; j < 4; ++j) LDM4(fbm[0][j], stn + bOff + (uint32_t)(j * 256));
        }
        // MMA slice1 (buffer1)
        #pragma unroll
        for (int m = 0; m < 4; ++m)
            #pragma unroll
            for (int j = 0; j < 4; ++j) {
                MMAI8(acc[m][2 * j],     fam[1][m], fbm[1][j][0], fbm[1][j][1]);
                MMAI8(acc[m][2 * j + 1], fam[1][m], fbm[1][j][2], fbm[1][j][3]);
            }
    }

    // ---- epilogue: branchless u32-packed top2 over warp's 64 cols -----------
    const int tig = lane & 3;
    const int colBase = ct * BN + wc * 64 + tig * 2;
    const unsigned invBase = 4095u - (unsigned)colBase;
    float sb2[8][2], hc[8][2];
    #pragma unroll
    for (int nf = 0; nf < 8; ++nf) {
        sb2[nf][0] = __ldg(&g_sB[colBase + nf * 8]);
        sb2[nf][1] = __ldg(&g_sB[colBase + nf * 8 + 1]);
        hc[nf][0]  = __ldg(&g_halfcsq[colBase + nf * 8]);
        hc[nf][1]  = __ldg(&g_halfcsq[colBase + nf * 8 + 1]);
    }
    #pragma unroll
    for (int m = 0; m < 4; ++m) {
        #pragma unroll
        for (int rv = 0; rv < 2; ++rv) {
            const int row = rt * BM + wr * 64 + m * 16 + (lane >> 2) + rv * 8;
            const float sa = __ldg(&g_sA[row]);
            unsigned b1 = 0u, b2 = 0u;
            #pragma unroll
            for (int nf = 0; nf < 8; ++nf)
                #pragma unroll
                for (int q = 0; q < 2; ++q) {
                    float t = (float)acc[m][nf][2 * rv + q] * sb2[nf][q];
                    float s = fmaf(t, sa, -hc[nf][q]);
                    unsigned p = (f2sortable_bl(s) & 0xFFFFF000u) |
                                 (invBase - (unsigned)(nf * 8 + q));
                    b2 = max(b2, min(b1, p));
                    b1 = max(b1, p);
                }
            #pragma unroll
            for (int o = 1; o < 4; o <<= 1) {
                unsigned o1 = __shfl_xor_sync(0xffffffffu, b1, o);
                unsigned o2 = __shfl_xor_sync(0xffffffffu, b2, o);
                b2 = max(max(b2, o2), min(b1, o1));
                b1 = max(b1, o1);
            }
            if (tig == 0) {
                const size_t base = ((size_t)row * NGRP + (ct * 2 + wc)) * 2;
                g_cand[base]     = b1;
                g_cand[base + 1] = b2;
            }
        }
    }
}

// ---------------- reduce (warp per row, u32 branchless) ----------------------
__global__ void k_reduce() {
    const int lane = threadIdx.x & 31;
    const int row  = blockIdx.x * 8 + (threadIdx.x >> 5);
    if (row >= NROWS) return;
    const unsigned* c = g_cand + (size_t)row * NGRP * 2;
    unsigned b1 = 0u, b2 = 0u;
    #pragma unroll
    for (int k = 0; k < 4; ++k) {
        unsigned v = c[lane + 32 * k];
        b2 = max(b2, min(b1, v));
        b1 = max(b1, v);
    }
    #pragma unroll
    for (int o = 16; o > 0; o >>= 1) {
        unsigned o1 = __shfl_xor_sync(0xffffffffu, b1, o);
        unsigned o2 = __shfl_xor_sync(0xffffffffu, b2, o);
        b2 = max(max(b2, o2), min(b1, o1));
        b1 = max(b1, o1);
    }
    if (lane == 0) {
        g_idx[row] = 4095 - (int)(b1 & 0xFFFu);
        float s1 = sortable2f(b1 & 0xFFFFF000u);
        float s2 = sortable2f(b2 & 0xFFFFF000u);
        if (s1 - s2 < THRESH) {
            int slot = atomicAdd(&g_flag_count, 1);
            if (slot < NROWS) g_flag_list[slot] = row;
        }
    }
}

// ---------------- rescue: exact fp32 re-rank of candidate set ----------------
#define CLIST_MAX 128
__global__ void __launch_bounds__(256)
k_rescue(const float* __restrict__ A, const float* __restrict__ B) {
    __shared__ float xrow[D];
    __shared__ unsigned samax;
    __shared__ unsigned long long sbest;
    __shared__ int clist[CLIST_MAX];
    __shared__ int ccount;
    const int tid = threadIdx.x, wid = tid >> 5, lid = tid & 31;
    const int count = min(g_flag_count, NROWS);
    for (int i = blockIdx.x; i < count; i += gridDim.x) {
        const int row = g_flag_list[i];
        __syncthreads();
        if (tid == 0) { samax = 0u; sbest = 0ull; ccount = 0; }
        for (int j = tid; j < D; j += 256) xrow[j] = A[(size_t)row * D + j];
        __syncthreads();
        const unsigned* c = g_cand + (size_t)row * NGRP * 2;
        unsigned amax = 0u;
        for (int e = tid; e < NGRP * 2; e += 256) {
            unsigned v = c[e];
            if (v > amax) amax = v;
        }
        atomicMax(&samax, amax);
        __syncthreads();
        const unsigned thrU =
            f2sortable(sortable2f(samax & 0xFFFFF000u) - THRESH) & 0xFFFFF000u;
        for (int e = tid; e < NGRP * 2; e += 256) {
            unsigned v = c[e];
            if ((v & 0xFFFFF000u) >= thrU) {
                int slot = atomicAdd(&ccount, 1);
                if (slot < CLIST_MAX)
                    clist[slot] = 4095 - (int)(v & 0xFFFu);
            }
        }
        __syncthreads();
        const int nc = min(ccount, CLIST_MAX);
        for (int k = wid; k < nc; k += 8) {
            const int m = clist[k];
            const float* cp = B + (size_t)m * D;
            float s = 0.f;
            #pragma unroll
            for (int t = 0; t < 4; ++t) {
                float4 cv = *(const float4*)(cp + t * 128 + lid * 4);
                float4 xv = *(const float4*)(xrow + t * 128 + lid * 4);
                s += cv.x * xv.x + cv.y * xv.y + cv.z * xv.z + cv.w * xv.w;
            }
            #pragma unroll
            for (int o = 16; o > 0; o >>= 1) s += __shfl_xor_sync(0xffffffffu, s, o);
            if (lid == 0) atomicMax(&sbest, packSI(s - __ldg(&g_halfcsq[m]), m));
        }
        __syncthreads();
        if (tid == 0)
            g_idx[row] = (int)(0xFFFFFFFFu - (unsigned)(sbest & 0xFFFFFFFFull));
    }
}

__global__ void k_gather(const float* __restrict__ cb, float* __restrict__ out,
                         float* __restrict__ idx_out) {
    int n = blockIdx.x;
    int idx = g_idx[n];
    const float4* src = (const float4*)(cb + (size_t)idx * D);
    float4* dst = (float4*)(out + (size_t)n * D);
    dst[threadIdx.x] = src[threadIdx.x];
    if (threadIdx.x == 0 && idx_out) idx_out[n] = (float)idx;
}

// ---------------- launch ----------------------------------------------------
extern "C" void kernel_launch(void* const* d_in, const int* in_sizes, int n_in,
                              void* d_out, int out_size) {
    const float* emb = (const float*)d_in[0];   // [65536, 512] f32
    const float* cb  = (const float*)d_in[1];   // [4096, 512]  f32
    float* out = (float*)d_out;

    float* idx_out = nullptr;
    long long need = (long long)NROWS * D + NROWS;
    if ((long long)out_size >= need) idx_out = out + (size_t)NROWS * D;

    cudaFuncSetAttribute(k_gemm, cudaFuncAttributeMaxDynamicSharedMemorySize, SMEM_TOTAL);

    k_init<<<1, 32>>>();
    k_quant_a<<<NROWS / 8, 256>>>(emb);
    k_quant_b<<<MCODES / 8, 256>>>(cb);

    dim3 grid(NT_C, NT_R);                      // (32, 512), ct fastest
    k_gemm<<<grid, 128, SMEM_TOTAL>>>();

    k_reduce<<<NROWS / 8, 256>>>();
    k_rescue<<<4096, 256>>>(emb, cb);
    k_gather<<<NROWS, 128>>>(cb, out, idx_out);
}

// round 17
// speedup vs baseline: 1.7280x; 1.0732x over previous
#include <cuda_runtime.h>
#include <cstdint>

#define D        512
#define NROWS    65536
#define MCODES   4096
#define BM       128
#define BN       128
#define NKC32    16              // k32 blocks (quant layout)
#define NST      8               // BK=64 stages
#define NT_R     512
#define NT_C     32
#define NGRP     64              // 64-col groups per row
#define THRESH   2.5f

// ---------------- scratch (device globals) -----------------------------------
#define A_BLK 4096               // 128 rows x 32 int8 per (rt,kc32)
#define B_BLK 4096
__device__ __align__(128) unsigned char qA[(size_t)NT_R * NKC32 * A_BLK]; // 32MB
__device__ __align__(128) unsigned char qB[(size_t)NT_C * NKC32 * B_BLK]; // 2MB

__device__ float        g_sA[NROWS];
__device__ float        g_sB[MCODES];
__device__ float        g_halfcsq[MCODES];
__device__ unsigned int g_cand[(size_t)NROWS * NGRP * 2];  // 33MB, u32 packed
__device__ int          g_idx[NROWS];
__device__ int          g_flag_count;
__device__ int          g_flag_list[NROWS];

// ---------------- helpers ----------------------------------------------------
__device__ __forceinline__ unsigned int f2sortable(float f) {
    unsigned int u = __float_as_uint(f);
    return (u & 0x80000000u) ? ~u : (u | 0x80000000u);
}
__device__ __forceinline__ float sortable2f(unsigned int u) {
    unsigned int b = (u & 0x80000000u) ? (u ^ 0x80000000u) : ~u;
    return __uint_as_float(b);
}
__device__ __forceinline__ unsigned long long packSI(float s, int col) {
    return ((unsigned long long)f2sortable(s) << 32) |
           (unsigned long long)(0xFFFFFFFFu - (unsigned)col);
}
__device__ __forceinline__ unsigned int f2sortable_bl(float f) {
    unsigned int u = __float_as_uint(f);
    return u ^ (0x80000000u | (unsigned int)((int)u >> 31));
}
__device__ __forceinline__ uint32_t smem_u32(const void* p) {
    uint32_t a;
    asm("{ .reg .u64 t; cvta.to.shared.u64 t, %1; cvt.u32.u64 %0, t; }" : "=r"(a) : "l"(p));
    return a;
}

// ---------------- cp.async / ldmatrix / mma ----------------------------------
__device__ __forceinline__ void cp16(uint32_t dst, const void* src) {
    asm volatile("cp.async.cg.shared.global [%0], [%1], 16;" :: "r"(dst), "l"(src) : "memory");
}
#define CP_COMMIT() asm volatile("cp.async.commit_group;" ::: "memory")
#define CP_WAIT(N)  asm volatile("cp.async.wait_group %0;" :: "n"(N) : "memory")

#define LDM4(r, addr) \
    asm volatile("ldmatrix.sync.aligned.m8n8.x4.shared.b16 {%0,%1,%2,%3}, [%4];" \
        : "=r"((r)[0]), "=r"((r)[1]), "=r"((r)[2]), "=r"((r)[3]) : "r"(addr))

#define MMAI8(d, a, b0_, b1_) \
    asm volatile("mma.sync.aligned.m16n8k32.row.col.s32.s8.s8.s32 " \
        "{%0,%1,%2,%3},{%4,%5,%6,%7},{%8,%9},{%0,%1,%2,%3};" \
        : "+r"((d)[0]), "+r"((d)[1]), "+r"((d)[2]), "+r"((d)[3]) \
        : "r"((a)[0]), "r"((a)[1]), "r"((a)[2]), "r"((a)[3]), "r"(b0_), "r"(b1_))

// ---------------- stage layout -----------------------------------------------
#define STG    16384
#define NSTAGE 4
#define SMEM_TOTAL (NSTAGE * STG)   // 65536

// ---------------- quantization (single digit) --------------------------------
__device__ __forceinline__ uint32_t pack4(int q0, int q1, int q2, int q3) {
    return (uint32_t)(q0 & 0xFF) | ((uint32_t)(q1 & 0xFF) << 8) |
           ((uint32_t)(q2 & 0xFF) << 16) | ((uint32_t)(q3 & 0xFF) << 24);
}

__device__ __forceinline__ void quant_row(const float* __restrict__ X, int row,
                                          unsigned char* __restrict__ pq,
                                          float* __restrict__ scale_out,
                                          float* __restrict__ halfcsq_out) {
    const int lane = threadIdx.x & 31;
    const float4* xp = (const float4*)(X + (size_t)row * D + lane * 16);
    float4 v[4];
    float amax = 0.f, ssq = 0.f;
    #pragma unroll
    for (int i = 0; i < 4; ++i) {
        v[i] = xp[i];
        amax = fmaxf(amax, fmaxf(fmaxf(fabsf(v[i].x), fabsf(v[i].y)),
                                 fmaxf(fabsf(v[i].z), fabsf(v[i].w))));
        if (halfcsq_out)
            ssq += v[i].x * v[i].x + v[i].y * v[i].y + v[i].z * v[i].z + v[i].w * v[i].w;
    }
    #pragma unroll
    for (int o = 16; o > 0; o >>= 1) {
        amax = fmaxf(amax, __shfl_xor_sync(0xffffffffu, amax, o));
        if (halfcsq_out) ssq += __shfl_xor_sync(0xffffffffu, ssq, o);
    }
    amax = fmaxf(amax, 1e-30f);
    const float inv = 127.f / amax;
    uint32_t H[4];
    #pragma unroll
    for (int i = 0; i < 4; ++i) {
        float f[4] = {v[i].x, v[i].y, v[i].z, v[i].w};
        int qh[4];
        #pragma unroll
        for (int j = 0; j < 4; ++j) {
            qh[j] = __float2int_rn(f[j] * inv);
            qh[j] = max(-127, min(127, qh[j]));
        }
        H[i] = pack4(qh[0], qh[1], qh[2], qh[3]);
    }
    const int rt  = row >> 7;
    const int rIn = row & 127;
    const int kc  = lane >> 1;
    const int c   = lane & 1;
    const size_t off = (size_t)(rt * NKC32 + kc) * 4096 + (size_t)(c * 128 + rIn) * 16;
    *(uint4*)(pq + off) = make_uint4(H[0], H[1], H[2], H[3]);
    if (lane == 0) {
        scale_out[row] = amax / 127.f;
        if (halfcsq_out) halfcsq_out[row] = 0.5f * ssq;
    }
}

__global__ void k_quant_a(const float* __restrict__ A) {
    int row = blockIdx.x * 8 + (threadIdx.x >> 5);
    if (row < NROWS) quant_row(A, row, qA, g_sA, nullptr);
}
__global__ void k_quant_b(const float* __restrict__ B) {
    int row = blockIdx.x * 8 + (threadIdx.x >> 5);
    if (row < MCODES) quant_row(B, row, qB, g_sB, g_halfcsq);
}

__global__ void k_init() { if (threadIdx.x == 0) g_flag_count = 0; }

// ---------------- main GEMM: 3 CTAs/SM, lean register footprint --------------
// 128 thr (4 warps, 2x2), warp tile 64x64, CTA 128x128.
// B fragments loaded one j-tile (4 regs) at a time to fit 170 regs.
__global__ void __launch_bounds__(128, 3)
k_gemm() {
    extern __shared__ char smem[];
    const uint32_t sb = smem_u32(smem);
    const int tid  = threadIdx.x;
    const int wid  = tid >> 5;
    const int lane = tid & 31;
    const int ct = blockIdx.x;           // 0..31 fastest -> B fully L2-resident
    const int rt = blockIdx.y;           // 0..511
    const int wr = wid >> 1;
    const int wc = wid & 1;

    const unsigned char* aP = qA + (size_t)(rt * NKC32) * A_BLK;
    const unsigned char* bP = qB + (size_t)(ct * NKC32) * B_BLK;

    auto load_stage = [&](int s) {
        const uint32_t st = sb + (s & (NSTAGE - 1)) * STG;
        const uint32_t o = tid * 16;
        const unsigned char* pa = aP + (size_t)(2 * s) * A_BLK;
        const unsigned char* pb = bP + (size_t)(2 * s) * B_BLK;
        #pragma unroll
        for (int i = 0; i < 4; ++i)
            cp16(st + o + i * 2048, pa + o + i * 2048);
        #pragma unroll
        for (int i = 0; i < 4; ++i)
            cp16(st + 8192 + o + i * 2048, pb + o + i * 2048);
    };

    const int mtx = lane >> 3;
    const uint32_t aOff = (uint32_t)((mtx >> 1) * 2048 +
                          (wr * 64 + (mtx & 1) * 8 + (lane & 7)) * 16);
    const uint32_t bOff = (uint32_t)(8192 + (mtx & 1) * 2048 +
                          (wc * 64 + (mtx >> 1) * 8 + (lane & 7)) * 16);

    int acc[4][8][4];
    #pragma unroll
    for (int m = 0; m < 4; ++m)
        #pragma unroll
        for (int n = 0; n < 8; ++n)
            #pragma unroll
            for (int q = 0; q < 4; ++q) acc[m][n][q] = 0;

    load_stage(0); CP_COMMIT();
    load_stage(1); CP_COMMIT();
    load_stage(2); CP_COMMIT();

    #pragma unroll 1
    for (int s = 0; s < NST; ++s) {
        if (s < NST - 2)       { CP_WAIT(2); }
        else if (s == NST - 2) { CP_WAIT(1); }
        else                   { CP_WAIT(0); }
        __syncthreads();
        if (s + 3 < NST) { load_stage(s + 3); CP_COMMIT(); }

        const uint32_t st = sb + (s & (NSTAGE - 1)) * STG;
        #pragma unroll
        for (int half = 0; half < 2; ++half) {
            const uint32_t hb = st + (uint32_t)(half * 4096);
            uint32_t fa[4][4];
            #pragma unroll
            for (int m = 0; m < 4; ++m) LDM4(fa[m], hb + aOff + (uint32_t)(m * 256));
            #pragma unroll
            for (int j = 0; j < 4; ++j) {
                uint32_t fb[4];
                LDM4(fb, hb + bOff + (uint32_t)(j * 256));
                #pragma unroll
                for (int m = 0; m < 4; ++m) {
                    MMAI8(acc[m][2 * j],     fa[m], fb[0], fb[1]);
                    MMAI8(acc[m][2 * j + 1], fa[m], fb[2], fb[3]);
                }
            }
        }
    }

    // ---- epilogue: branchless u32-packed top2 over warp's 64 cols -----------
    const int tig = lane & 3;
    const int colBase = ct * BN + wc * 64 + tig * 2;
    const unsigned invBase = 4095u - (unsigned)colBase;
    float sb2[8][2], hc[8][2];
    #pragma unroll
    for (int nf = 0; nf < 8; ++nf) {
        sb2[nf][0] = __ldg(&g_sB[colBase + nf * 8]);
        sb2[nf][1] = __ldg(&g_sB[colBase + nf * 8 + 1]);
        hc[nf][0]  = __ldg(&g_halfcsq[colBase + nf * 8]);
        hc[nf][1]  = __ldg(&g_halfcsq[colBase + nf * 8 + 1]);
    }
    #pragma unroll
    for (int m = 0; m < 4; ++m) {
        #pragma unroll
        for (int rv = 0; rv < 2; ++rv) {
            const int row = rt * BM + wr * 64 + m * 16 + (lane >> 2) + rv * 8;
            const float sa = __ldg(&g_sA[row]);
            unsigned b1 = 0u, b2 = 0u;
            #pragma unroll
            for (int nf = 0; nf < 8; ++nf)
                #pragma unroll
                for (int q = 0; q < 2; ++q) {
                    float t = (float)acc[m][nf][2 * rv + q] * sb2[nf][q];
                    float s = fmaf(t, sa, -hc[nf][q]);
                    unsigned p = (f2sortable_bl(s) & 0xFFFFF000u) |
                                 (invBase - (unsigned)(nf * 8 + q));
                    b2 = max(b2, min(b1, p));
                    b1 = max(b1, p);
                }
            #pragma unroll
            for (int o = 1; o < 4; o <<= 1) {
                unsigned o1 = __shfl_xor_sync(0xffffffffu, b1, o);
                unsigned o2 = __shfl_xor_sync(0xffffffffu, b2, o);
                b2 = max(max(b2, o2), min(b1, o1));
                b1 = max(b1, o1);
            }
            if (tig == 0) {
                const size_t base = ((size_t)row * NGRP + (ct * 2 + wc)) * 2;
                g_cand[base]     = b1;
                g_cand[base + 1] = b2;
            }
        }
    }
}

// ---------------- reduce (warp per row, u32 branchless) ----------------------
__global__ void k_reduce() {
    const int lane = threadIdx.x & 31;
    const int row  = blockIdx.x * 8 + (threadIdx.x >> 5);
    if (row >= NROWS) return;
    const unsigned* c = g_cand + (size_t)row * NGRP * 2;
    unsigned b1 = 0u, b2 = 0u;
    #pragma unroll
    for (int k = 0; k < 4; ++k) {
        unsigned v = c[lane + 32 * k];
        b2 = max(b2, min(b1, v));
        b1 = max(b1, v);
    }
    #pragma unroll
    for (int o = 16; o > 0; o >>= 1) {
        unsigned o1 = __shfl_xor_sync(0xffffffffu, b1, o);
        unsigned o2 = __shfl_xor_sync(0xffffffffu, b2, o);
        b2 = max(max(b2, o2), min(b1, o1));
        b1 = max(b1, o1);
    }
    if (lane == 0) {
        g_idx[row] = 4095 - (int)(b1 & 0xFFFu);
        float s1 = sortable2f(b1 & 0xFFFFF000u);
        float s2 = sortable2f(b2 & 0xFFFFF000u);
        if (s1 - s2 < THRESH) {
            int slot = atomicAdd(&g_flag_count, 1);
            if (slot < NROWS) g_flag_list[slot] = row;
        }
    }
}

// ---------------- rescue: exact fp32 re-rank of candidate set ----------------
#define CLIST_MAX 128
__global__ void __launch_bounds__(256)
k_rescue(const float* __restrict__ A, const float* __restrict__ B) {
    __shared__ float xrow[D];
    __shared__ unsigned samax;
    __shared__ unsigned long long sbest;
    __shared__ int clist[CLIST_MAX];
    __shared__ int ccount;
    const int tid = threadIdx.x, wid = tid >> 5, lid = tid & 31;
    const int count = min(g_flag_count, NROWS);
    for (int i = blockIdx.x; i < count; i += gridDim.x) {
        const int row = g_flag_list[i];
        __syncthreads();
        if (tid == 0) { samax = 0u; sbest = 0ull; ccount = 0; }
        for (int j = tid; j < D; j += 256) xrow[j] = A[(size_t)row * D + j];
        __syncthreads();
        const unsigned* c = g_cand + (size_t)row * NGRP * 2;
        unsigned amax = 0u;
        for (int e = tid; e < NGRP * 2; e += 256) {
            unsigned v = c[e];
            if (v > amax) amax = v;
        }
        atomicMax(&samax, amax);
        __syncthreads();
        const unsigned thrU =
            f2sortable(sortable2f(samax & 0xFFFFF000u) - THRESH) & 0xFFFFF000u;
        for (int e = tid; e < NGRP * 2; e += 256) {
            unsigned v = c[e];
            if ((v & 0xFFFFF000u) >= thrU) {
                int slot = atomicAdd(&ccount, 1);
                if (slot < CLIST_MAX)
                    clist[slot] = 4095 - (int)(v & 0xFFFu);
            }
        }
        __syncthreads();
        const int nc = min(ccount, CLIST_MAX);
        for (int k = wid; k < nc; k += 8) {
            const int m = clist[k];
            const float* cp = B + (size_t)m * D;
            float s = 0.f;
            #pragma unroll
            for (int t = 0; t < 4; ++t) {
                float4 cv = *(const float4*)(cp + t * 128 + lid * 4);
                float4 xv = *(const float4*)(xrow + t * 128 + lid * 4);
                s += cv.x * xv.x + cv.y * xv.y + cv.z * xv.z + cv.w * xv.w;
            }
            #pragma unroll
            for (int o = 16; o > 0; o >>= 1) s += __shfl_xor_sync(0xffffffffu, s, o);
            if (lid == 0) atomicMax(&sbest, packSI(s - __ldg(&g_halfcsq[m]), m));
        }
        __syncthreads();
        if (tid == 0)
            g_idx[row] = (int)(0xFFFFFFFFu - (unsigned)(sbest & 0xFFFFFFFFull));
    }
}

// ---------------- gather: 8 rows per 256-thr block, idx prefetched -----------
__global__ void __launch_bounds__(256)
k_gather(const float* __restrict__ cb, float* __restrict__ out,
         float* __restrict__ idx_out) {
    __shared__ int sidx[8];
    const int base = blockIdx.x * 8;
    const int wid = threadIdx.x >> 5, lane = threadIdx.x & 31;
    if (threadIdx.x < 8) sidx[threadIdx.x] = g_idx[base + threadIdx.x];
    __syncthreads();
    const int row = base + wid;
    const int idx = sidx[wid];
    const float4* src = (const float4*)(cb + (size_t)idx * D);
    float4* dst = (float4*)(out + (size_t)row * D);
    float4 v0 = src[lane], v1 = src[lane + 32], v2 = src[lane + 64], v3 = src[lane + 96];
    dst[lane] = v0; dst[lane + 32] = v1; dst[lane + 64] = v2; dst[lane + 96] = v3;
    if (lane == 0 && idx_out) idx_out[row] = (float)idx;
}

// ---------------- launch ----------------------------------------------------
extern "C" void kernel_launch(void* const* d_in, const int* in_sizes, int n_in,
                              void* d_out, int out_size) {
    const float* emb = (const float*)d_in[0];   // [65536, 512] f32
    const float* cb  = (const float*)d_in[1];   // [4096, 512]  f32
    float* out = (float*)d_out;

    float* idx_out = nullptr;
    long long need = (long long)NROWS * D + NROWS;
    if ((long long)out_size >= need) idx_out = out + (size_t)NROWS * D;

    cudaFuncSetAttribute(k_gemm, cudaFuncAttributeMaxDynamicSharedMemorySize, SMEM_TOTAL);

    k_init<<<1, 32>>>();
    k_quant_a<<<NROWS / 8, 256>>>(emb);
    k_quant_b<<<MCODES / 8, 256>>>(cb);

    dim3 grid(NT_C, NT_R);                      // (32, 512), ct fastest
    k_gemm<<<grid, 128, SMEM_TOTAL>>>();

    k_reduce<<<NROWS / 8, 256>>>();
    k_rescue<<<4096, 256>>>(emb, cb);
    k_gather<<<NROWS / 8, 256>>>(cb, out, idx_out);
}